// round 2
// baseline (speedup 1.0000x reference)
#include <cuda_runtime.h>

#define NN   100000
#define EE   1600000
#define DIN  128
#define F    64        // H*C
#define NEGS 0.2f

static const int NCHUNK = (NN + 1023) / 1024;   // 98

// ---------------- scratch (device globals; no allocs allowed) ----------------
__device__ float g_bufA[NN * F];
__device__ float g_bufB[NN * F];
__device__ int   g_deg[NN];
__device__ int   g_cur[NN];
__device__ int   g_off[NN];
__device__ int   g_csr[EE];
__device__ int   g_csum[128];
__device__ int   g_cbase[128];

// ---------------- CSR build ----------------
__global__ void k_zero() {
    int i = blockIdx.x * blockDim.x + threadIdx.x;
    if (i < NN) { g_deg[i] = 0; g_cur[i] = 0; }
}

__global__ void k_degree(const int* __restrict__ ei) {
    int e = blockIdx.x * blockDim.x + threadIdx.x;
    if (e < EE) atomicAdd(&g_deg[ei[EE + e]], 1);
}

__global__ void k_chunksum() {
    __shared__ int sh[256];
    int base = blockIdx.x * 1024;
    int acc = 0;
    for (int i = threadIdx.x; i < 1024; i += 256) {
        int gi = base + i;
        if (gi < NN) acc += g_deg[gi];
    }
    sh[threadIdx.x] = acc;
    __syncthreads();
    for (int s = 128; s > 0; s >>= 1) {
        if (threadIdx.x < s) sh[threadIdx.x] += sh[threadIdx.x + s];
        __syncthreads();
    }
    if (threadIdx.x == 0) g_csum[blockIdx.x] = sh[0];
}

__global__ void k_scanbase(int nch) {
    if (threadIdx.x == 0) {
        int acc = 0;
        for (int i = 0; i < nch; i++) { g_cbase[i] = acc; acc += g_csum[i]; }
    }
}

__global__ void k_scanchunk() {
    __shared__ int sh[1024];
    int gi = blockIdx.x * 1024 + threadIdx.x;
    int v = (gi < NN) ? g_deg[gi] : 0;
    sh[threadIdx.x] = v;
    __syncthreads();
    for (int s = 1; s < 1024; s <<= 1) {
        int t = (threadIdx.x >= s) ? sh[threadIdx.x - s] : 0;
        __syncthreads();
        sh[threadIdx.x] += t;
        __syncthreads();
    }
    if (gi < NN) g_off[gi] = g_cbase[blockIdx.x] + sh[threadIdx.x] - v;  // exclusive
}

__global__ void k_fill(const int* __restrict__ ei) {
    int e = blockIdx.x * blockDim.x + threadIdx.x;
    if (e < EE) {
        int src = ei[e];
        int dst = ei[EE + e];
        int slot = g_off[dst] + atomicAdd(&g_cur[dst], 1);
        g_csr[slot] = src;
    }
}

// ---------------- dense GEMM: Y[N,64] = X[N,K] @ W[64,K]^T + b ----------------
template <int K>
__global__ void k_gemm(const float* __restrict__ X, const float* __restrict__ W,
                       const float* __restrict__ b, float* __restrict__ Y) {
    __shared__ float Ws[64][K + 1];   // +1 pad -> conflict-free column reads
    __shared__ float Xs[4][K];
    int tid = threadIdx.x;
    for (int i = tid; i < 64 * K; i += 256) Ws[i / K][i % K] = W[i];
    int row0 = blockIdx.x * 4;
    for (int i = tid; i < 4 * K; i += 256) {
        int r = i / K, k = i % K;
        int n = row0 + r;
        Xs[r][k] = (n < NN) ? X[n * K + k] : 0.f;
    }
    __syncthreads();
    int r = tid >> 6, j = tid & 63;
    int n = row0 + r;
    if (n >= NN) return;
    float acc = b[j];
#pragma unroll
    for (int k = 0; k < K; k++) acc = fmaf(Xs[r][k], Ws[j][k], acc);
    Y[n * 64 + j] = acc;
}

// ---------------- fused GAT aggregation (softmax+weighted sum), one warp/node --
// out_c[i] = relu( sum_e exp(leaky(aR_c*x_ic + aL_c*x_sc)) * x_sc / (sum_e exp(...) + 1e-16) )
__global__ void k_agg(const float* __restrict__ xl, const float* __restrict__ attL,
                      const float* __restrict__ attR, float* __restrict__ out) {
    int node = (blockIdx.x * blockDim.x + threadIdx.x) >> 5;
    if (node >= NN) return;
    int lane = threadIdx.x & 31;
    const float2* xl2 = (const float2*)xl;
    float2 aL = __ldg(((const float2*)attL) + lane);
    float2 aR = __ldg(((const float2*)attR) + lane);
    float2 xi = __ldg(xl2 + node * 32 + lane);
    float ar0 = aR.x * xi.x;
    float ar1 = aR.y * xi.y;
    float n0 = 0.f, n1 = 0.f, d0 = 0.f, d1 = 0.f;
    int s0 = g_off[node];
    int deg = g_deg[node];
    for (int base = 0; base < deg; base += 32) {
        int cnt = min(32, deg - base);
        int myidx = (lane < cnt) ? __ldg(g_csr + s0 + base + lane) : 0;
        for (int k = 0; k < cnt; k++) {
            int s = __shfl_sync(0xffffffffu, myidx, k);
            float2 xs = __ldg(xl2 + s * 32 + lane);
            float e0 = fmaf(aL.x, xs.x, ar0);
            float e1 = fmaf(aL.y, xs.y, ar1);
            e0 = (e0 >= 0.f) ? e0 : NEGS * e0;
            e1 = (e1 >= 0.f) ? e1 : NEGS * e1;
            float p0 = __expf(e0);
            float p1 = __expf(e1);
            n0 = fmaf(p0, xs.x, n0); d0 += p0;
            n1 = fmaf(p1, xs.y, n1); d1 += p1;
        }
    }
    float o0 = fmaxf(n0 / (d0 + 1e-16f), 0.f);   // fused outer relu
    float o1 = fmaxf(n1 / (d1 + 1e-16f), 0.f);
    ((float2*)out)[node * 32 + lane] = make_float2(o0, o1);
}

// ---------------- post-MP: h[64] -> 32 -> 40 -> log_softmax ----------------
__global__ void k_post(const float* __restrict__ h, const float* __restrict__ Wp1,
                       const float* __restrict__ bp1, const float* __restrict__ Wp2,
                       const float* __restrict__ bp2, float* __restrict__ out) {
    __shared__ float sW1[32 * 64];
    __shared__ float sW2[40 * 32];
    __shared__ float sb1[32], sb2[40];
    int tid = threadIdx.x;
    for (int i = tid; i < 32 * 64; i += 256) sW1[i] = Wp1[i];
    for (int i = tid; i < 40 * 32; i += 256) sW2[i] = Wp2[i];
    if (tid < 32) sb1[tid] = bp1[tid];
    if (tid < 40) sb2[tid] = bp2[tid];
    __syncthreads();
    int n = blockIdx.x * blockDim.x + tid;
    if (n >= NN) return;
    float hv[64];
    const float4* h4 = (const float4*)(h + n * 64);
#pragma unroll
    for (int i = 0; i < 16; i++) {
        float4 v = h4[i];
        hv[4 * i] = v.x; hv[4 * i + 1] = v.y; hv[4 * i + 2] = v.z; hv[4 * i + 3] = v.w;
    }
    float p1[32];
#pragma unroll
    for (int j = 0; j < 32; j++) {
        float acc = sb1[j];
#pragma unroll
        for (int c = 0; c < 64; c++) acc = fmaf(hv[c], sW1[j * 64 + c], acc);
        p1[j] = acc;
    }
    float z[40];
    float m = -1e30f;
#pragma unroll
    for (int o = 0; o < 40; o++) {
        float acc = sb2[o];
#pragma unroll
        for (int j = 0; j < 32; j++) acc = fmaf(p1[j], sW2[o * 32 + j], acc);
        z[o] = acc;
        m = fmaxf(m, acc);
    }
    float s = 0.f;
#pragma unroll
    for (int o = 0; o < 40; o++) s += __expf(z[o] - m);
    float lse = m + __logf(s);
#pragma unroll
    for (int o = 0; o < 40; o++) out[n * 40 + o] = z[o] - lse;
}

// ---------------- launch ----------------
extern "C" void kernel_launch(void* const* d_in, const int* in_sizes, int n_in,
                              void* d_out, int out_size) {
    const float* x   = (const float*)d_in[0];
    const int*   ei  = (const int*)d_in[1];
    const float* W1  = (const float*)d_in[2];
    const float* b1  = (const float*)d_in[3];
    const float* al1 = (const float*)d_in[4];
    const float* ar1 = (const float*)d_in[5];
    const float* W2  = (const float*)d_in[6];
    const float* b2  = (const float*)d_in[7];
    const float* al2 = (const float*)d_in[8];
    const float* ar2 = (const float*)d_in[9];
    const float* Wp1 = (const float*)d_in[10];
    const float* bp1 = (const float*)d_in[11];
    const float* Wp2 = (const float*)d_in[12];
    const float* bp2 = (const float*)d_in[13];
    float* out = (float*)d_out;

    float* bufA;  cudaGetSymbolAddress((void**)&bufA, g_bufA);
    float* bufB;  cudaGetSymbolAddress((void**)&bufB, g_bufB);

    // CSR build (same topology both layers; rebuilt each call — cheap)
    k_zero<<<(NN + 255) / 256, 256>>>();
    k_degree<<<(EE + 255) / 256, 256>>>(ei);
    k_chunksum<<<NCHUNK, 256>>>();
    k_scanbase<<<1, 32>>>(NCHUNK);
    k_scanchunk<<<NCHUNK, 1024>>>();
    k_fill<<<(EE + 255) / 256, 256>>>(ei);

    // layer 1
    k_gemm<DIN><<<(NN + 3) / 4, 256>>>(x, W1, b1, bufA);
    k_agg<<<(NN * 32 + 255) / 256, 256>>>(bufA, al1, ar1, bufB);

    // layer 2
    k_gemm<F><<<(NN + 3) / 4, 256>>>(bufB, W2, b2, bufA);
    k_agg<<<(NN * 32 + 255) / 256, 256>>>(bufA, al2, ar2, bufB);

    // post-MP + log_softmax
    k_post<<<(NN + 255) / 256, 256>>>(bufB, Wp1, bp1, Wp2, bp2, out);
}

// round 3
// speedup vs baseline: 1.7436x; 1.7436x over previous
#include <cuda_runtime.h>

#define NN    100000
#define EE    1600000
#define DIN   128
#define F     64        // H*C
#define NEGS  0.2f
#define LOG2E 1.4426950408889634f
#define NCH   98        // ceil(NN/1024)

// ---------------- scratch (device globals; no allocs allowed) ----------------
__device__ float g_bufA[NN * F];
__device__ float g_bufB[NN * F];
__device__ int   g_deg[NN];
__device__ int   g_cur[NN];
__device__ int   g_off[NN];
__device__ int   g_csr[EE];
__device__ int   g_csum[128];
__device__ int   g_cbase[128];

// ---------------- CSR build ----------------
__global__ void k_zero() {
    int i = blockIdx.x * blockDim.x + threadIdx.x;
    if (i < NN) { g_deg[i] = 0; g_cur[i] = 0; }
}

__global__ void k_degree(const int* __restrict__ ei) {
    int e = blockIdx.x * blockDim.x + threadIdx.x;
    if (e < EE) atomicAdd(&g_deg[ei[EE + e]], 1);
}

__global__ void k_chunksum() {
    __shared__ int sh[256];
    int base = blockIdx.x * 1024;
    int acc = 0;
    for (int i = threadIdx.x; i < 1024; i += 256) {
        int gi = base + i;
        if (gi < NN) acc += g_deg[gi];
    }
    sh[threadIdx.x] = acc;
    __syncthreads();
    for (int s = 128; s > 0; s >>= 1) {
        if (threadIdx.x < s) sh[threadIdx.x] += sh[threadIdx.x + s];
        __syncthreads();
    }
    if (threadIdx.x == 0) g_csum[blockIdx.x] = sh[0];
}

// parallel scan of the 98 chunk sums (replaces 9.5us serial loop)
__global__ void k_scanbase() {
    __shared__ int sh[128];
    int t = threadIdx.x;
    int v = (t < NCH) ? g_csum[t] : 0;
    sh[t] = v;
    __syncthreads();
    for (int s = 1; s < 128; s <<= 1) {
        int u = (t >= s) ? sh[t - s] : 0;
        __syncthreads();
        sh[t] += u;
        __syncthreads();
    }
    if (t < NCH) g_cbase[t] = sh[t] - v;   // exclusive
}

__global__ void k_scanchunk() {
    __shared__ int sh[1024];
    int gi = blockIdx.x * 1024 + threadIdx.x;
    int v = (gi < NN) ? g_deg[gi] : 0;
    sh[threadIdx.x] = v;
    __syncthreads();
    for (int s = 1; s < 1024; s <<= 1) {
        int t = (threadIdx.x >= s) ? sh[threadIdx.x - s] : 0;
        __syncthreads();
        sh[threadIdx.x] += t;
        __syncthreads();
    }
    if (gi < NN) g_off[gi] = g_cbase[blockIdx.x] + sh[threadIdx.x] - v;  // exclusive
}

__global__ void k_fill(const int* __restrict__ ei) {
    int e = blockIdx.x * blockDim.x + threadIdx.x;
    if (e < EE) {
        int src = ei[e];
        int dst = ei[EE + e];
        int slot = g_off[dst] + atomicAdd(&g_cur[dst], 1);
        g_csr[slot] = src;
    }
}

// ---------------- dense GEMM: Y[N,64] = X[N,K] @ W[64,K]^T + b ----------------
// 128 rows x 64 cols per block, 256 threads, 8x4 register tiles.
// W kept k-major in smem (broadcast reads), X row-strided (conflict-free LDS.128).
template <int K>
__global__ void __launch_bounds__(256) k_gemm(const float* __restrict__ X,
                                              const float* __restrict__ W,
                                              const float* __restrict__ b,
                                              float* __restrict__ Y) {
    extern __shared__ float smem[];
    const int XS = K + 4;                 // X row stride (floats), 16B-aligned
    float* sw = smem;                     // [K][68]  (k-major W)
    float* sx = smem + K * 68;            // [128][XS]
    int tid = threadIdx.x;

    // load W [64,K] row-major -> sw[k*68 + col]
    for (int i = tid; i < 64 * K; i += 256) {
        int col = i / K, k = i % K;
        sw[k * 68 + col] = W[i];
    }
    // load X rows [row0, row0+128) via float4
    int row0 = blockIdx.x * 128;
    int nrows = min(128, NN - row0);
    const float4* X4 = (const float4*)(X + (size_t)row0 * K);
    for (int i = tid; i < 128 * K / 4; i += 256) {
        int idx = i * 4;
        int r = idx / K, c = idx % K;
        float4 v = (r < nrows) ? X4[i] : make_float4(0.f, 0.f, 0.f, 0.f);
        *(float4*)&sx[r * XS + c] = v;
    }
    __syncthreads();

    int ty = tid & 15;        // row group: rows ty + 16*i, i<8
    int tx = tid >> 4;        // col group: cols 4*tx .. 4*tx+3
    float acc[8][4];
    float4 bias = *(const float4*)(b + 4 * tx);
#pragma unroll
    for (int i = 0; i < 8; i++) {
        acc[i][0] = bias.x; acc[i][1] = bias.y; acc[i][2] = bias.z; acc[i][3] = bias.w;
    }

#pragma unroll 4
    for (int kk = 0; kk < K; kk += 4) {
        float4 wv[4];
#pragma unroll
        for (int k4 = 0; k4 < 4; k4++)
            wv[k4] = *(const float4*)&sw[(kk + k4) * 68 + 4 * tx];
        float4 xv[8];
#pragma unroll
        for (int i = 0; i < 8; i++)
            xv[i] = *(const float4*)&sx[(ty + 16 * i) * XS + kk];
#pragma unroll
        for (int i = 0; i < 8; i++) {
#pragma unroll
            for (int j = 0; j < 4; j++) {
                float w0 = (&wv[0].x)[j], w1 = (&wv[1].x)[j],
                      w2 = (&wv[2].x)[j], w3 = (&wv[3].x)[j];
                acc[i][j] = fmaf(xv[i].x, w0, acc[i][j]);
                acc[i][j] = fmaf(xv[i].y, w1, acc[i][j]);
                acc[i][j] = fmaf(xv[i].z, w2, acc[i][j]);
                acc[i][j] = fmaf(xv[i].w, w3, acc[i][j]);
            }
        }
    }

#pragma unroll
    for (int i = 0; i < 8; i++) {
        int r = ty + 16 * i;
        if (r < nrows) {
            float4 v = make_float4(acc[i][0], acc[i][1], acc[i][2], acc[i][3]);
            *(float4*)&Y[(size_t)(row0 + r) * 64 + 4 * tx] = v;
        }
    }
}

// ---------------- fused GAT aggregation (softmax + weighted sum) --------------
// one warp per node; exp folded to exp2 (log2e premultiplied into att vectors)
__global__ void k_agg(const float* __restrict__ xl, const float* __restrict__ attL,
                      const float* __restrict__ attR, float* __restrict__ out) {
    int node = (blockIdx.x * blockDim.x + threadIdx.x) >> 5;
    if (node >= NN) return;
    int lane = threadIdx.x & 31;
    const float2* __restrict__ xl2 = (const float2*)xl;
    float2 aL = __ldg(((const float2*)attL) + lane);
    float2 aR = __ldg(((const float2*)attR) + lane);
    float aLx = aL.x * LOG2E, aLy = aL.y * LOG2E;
    float2 xi = __ldg(xl2 + (size_t)node * 32 + lane);
    float ar0 = aR.x * LOG2E * xi.x;
    float ar1 = aR.y * LOG2E * xi.y;
    float n0 = 0.f, n1 = 0.f, d0 = 0.f, d1 = 0.f;
    int s0 = g_off[node];
    int deg = g_deg[node];
    for (int base = 0; base < deg; base += 32) {
        int cnt = min(32, deg - base);
        int myidx = (lane < cnt) ? __ldg(g_csr + s0 + base + lane) : 0;
        int k = 0;
        for (; k + 4 <= cnt; k += 4) {
            int i0 = __shfl_sync(0xffffffffu, myidx, k);
            int i1 = __shfl_sync(0xffffffffu, myidx, k + 1);
            int i2 = __shfl_sync(0xffffffffu, myidx, k + 2);
            int i3 = __shfl_sync(0xffffffffu, myidx, k + 3);
            float2 x0 = __ldg(xl2 + (size_t)i0 * 32 + lane);
            float2 x1 = __ldg(xl2 + (size_t)i1 * 32 + lane);
            float2 x2 = __ldg(xl2 + (size_t)i2 * 32 + lane);
            float2 x3 = __ldg(xl2 + (size_t)i3 * 32 + lane);
#define EDGE(xs)                                                     \
            {                                                        \
                float e0 = fmaf(aLx, xs.x, ar0);                     \
                float e1 = fmaf(aLy, xs.y, ar1);                     \
                e0 = (e0 >= 0.f) ? e0 : NEGS * e0;                   \
                e1 = (e1 >= 0.f) ? e1 : NEGS * e1;                   \
                float p0 = exp2f(e0);                                \
                float p1 = exp2f(e1);                                \
                n0 = fmaf(p0, xs.x, n0); d0 += p0;                   \
                n1 = fmaf(p1, xs.y, n1); d1 += p1;                   \
            }
            EDGE(x0) EDGE(x1) EDGE(x2) EDGE(x3)
        }
        for (; k < cnt; k++) {
            int s = __shfl_sync(0xffffffffu, myidx, k);
            float2 xs = __ldg(xl2 + (size_t)s * 32 + lane);
            EDGE(xs)
        }
#undef EDGE
    }
    float o0 = fmaxf(n0 / (d0 + 1e-16f), 0.f);   // fused outer relu
    float o1 = fmaxf(n1 / (d1 + 1e-16f), 0.f);
    ((float2*)out)[(size_t)node * 32 + lane] = make_float2(o0, o1);
}

// ---------------- post-MP: h[64] -> 32 -> 40 -> log_softmax ----------------
__global__ void k_post(const float* __restrict__ h, const float* __restrict__ Wp1,
                       const float* __restrict__ bp1, const float* __restrict__ Wp2,
                       const float* __restrict__ bp2, float* __restrict__ out) {
    __shared__ float sW1[32 * 64];
    __shared__ float sW2[40 * 32];
    __shared__ float sb1[32], sb2[40];
    int tid = threadIdx.x;
    for (int i = tid; i < 32 * 64; i += 256) sW1[i] = Wp1[i];
    for (int i = tid; i < 40 * 32; i += 256) sW2[i] = Wp2[i];
    if (tid < 32) sb1[tid] = bp1[tid];
    if (tid < 40) sb2[tid] = bp2[tid];
    __syncthreads();
    int n = blockIdx.x * blockDim.x + tid;
    if (n >= NN) return;
    float hv[64];
    const float4* h4 = (const float4*)(h + (size_t)n * 64);
#pragma unroll
    for (int i = 0; i < 16; i++) {
        float4 v = h4[i];
        hv[4 * i] = v.x; hv[4 * i + 1] = v.y; hv[4 * i + 2] = v.z; hv[4 * i + 3] = v.w;
    }
    float p1[32];
#pragma unroll
    for (int j = 0; j < 32; j++) {
        float acc = sb1[j];
#pragma unroll
        for (int c = 0; c < 64; c++) acc = fmaf(hv[c], sW1[j * 64 + c], acc);
        p1[j] = acc;
    }
    float z[40];
    float m = -1e30f;
#pragma unroll
    for (int o = 0; o < 40; o++) {
        float acc = sb2[o];
#pragma unroll
        for (int j = 0; j < 32; j++) acc = fmaf(p1[j], sW2[o * 32 + j], acc);
        z[o] = acc;
        m = fmaxf(m, acc);
    }
    float s = 0.f;
#pragma unroll
    for (int o = 0; o < 40; o++) s += __expf(z[o] - m);
    float lse = m + __logf(s);
#pragma unroll
    for (int o = 0; o < 40; o++) out[(size_t)n * 40 + o] = z[o] - lse;
}

// ---------------- launch ----------------
extern "C" void kernel_launch(void* const* d_in, const int* in_sizes, int n_in,
                              void* d_out, int out_size) {
    const float* x   = (const float*)d_in[0];
    const int*   ei  = (const int*)d_in[1];
    const float* W1  = (const float*)d_in[2];
    const float* b1  = (const float*)d_in[3];
    const float* al1 = (const float*)d_in[4];
    const float* ar1 = (const float*)d_in[5];
    const float* W2  = (const float*)d_in[6];
    const float* b2  = (const float*)d_in[7];
    const float* al2 = (const float*)d_in[8];
    const float* ar2 = (const float*)d_in[9];
    const float* Wp1 = (const float*)d_in[10];
    const float* bp1 = (const float*)d_in[11];
    const float* Wp2 = (const float*)d_in[12];
    const float* bp2 = (const float*)d_in[13];
    float* out = (float*)d_out;

    float* bufA;  cudaGetSymbolAddress((void**)&bufA, g_bufA);
    float* bufB;  cudaGetSymbolAddress((void**)&bufB, g_bufB);

    const int smem1 = (DIN * 68 + 128 * (DIN + 4)) * 4;   // 102,400 B
    const int smem2 = (F * 68 + 128 * (F + 4)) * 4;       //  52,224 B
    cudaFuncSetAttribute(k_gemm<DIN>, cudaFuncAttributeMaxDynamicSharedMemorySize, smem1);
    cudaFuncSetAttribute(k_gemm<F>,   cudaFuncAttributeMaxDynamicSharedMemorySize, smem2);

    // CSR build (same topology both layers)
    k_zero<<<(NN + 255) / 256, 256>>>();
    k_degree<<<(EE + 255) / 256, 256>>>(ei);
    k_chunksum<<<NCH, 256>>>();
    k_scanbase<<<1, 128>>>();
    k_scanchunk<<<NCH, 1024>>>();
    k_fill<<<(EE + 255) / 256, 256>>>(ei);

    const int gblk = (NN + 127) / 128;   // 782

    // layer 1
    k_gemm<DIN><<<gblk, 256, smem1>>>(x, W1, b1, bufA);
    k_agg<<<(NN * 32 + 255) / 256, 256>>>(bufA, al1, ar1, bufB);

    // layer 2
    k_gemm<F><<<gblk, 256, smem2>>>(bufB, W2, b2, bufA);
    k_agg<<<(NN * 32 + 255) / 256, 256>>>(bufA, al2, ar2, bufB);

    // post-MP + log_softmax
    k_post<<<(NN + 255) / 256, 256>>>(bufB, Wp1, bp1, Wp2, bp2, out);
}